// round 5
// baseline (speedup 1.0000x reference)
#include <cuda_runtime.h>
#include <cuda_bf16.h>
#include <cuda_fp16.h>
#include <math.h>
#include <stdint.h>

#define BATCH 8
#define CH    256
#define NPIX  4096

// Split-plane scratch: value ~= hi + lo (bf16 planes for Q/K/W/X, fp16 for V)
static __device__ __nv_bfloat16 g_wh[3 * CH * CH];
static __device__ __nv_bfloat16 g_wl[3 * CH * CH];
static __device__ __nv_bfloat16 g_xth[(size_t)BATCH * NPIX * CH];
static __device__ __nv_bfloat16 g_xtl[(size_t)BATCH * NPIX * CH];
static __device__ __nv_bfloat16 g_qth[(size_t)BATCH * NPIX * CH];
static __device__ __nv_bfloat16 g_qtl[(size_t)BATCH * NPIX * CH];
static __device__ __nv_bfloat16 g_kth[(size_t)BATCH * NPIX * CH];
static __device__ __nv_bfloat16 g_ktl[(size_t)BATCH * NPIX * CH];
static __device__ __half        g_vph[(size_t)BATCH * CH * NPIX];
static __device__ __half        g_vpl[(size_t)BATCH * CH * NPIX];
static __device__ float         g_s [(size_t)BATCH * NPIX * NPIX];
static __device__ __half        g_ah[(size_t)BATCH * NPIX * NPIX];

__device__ __forceinline__ uint32_t smem_u32(const void* p) {
    uint32_t a;
    asm("{ .reg .u64 t; cvta.to.shared.u64 t, %1; cvt.u32.u64 %0, t; }" : "=r"(a) : "l"(p));
    return a;
}
__device__ __forceinline__ void cp16(uint32_t saddr, const void* g) {
    uint64_t ga;
    asm("cvta.to.global.u64 %0, %1;" : "=l"(ga) : "l"(g));
    asm volatile("cp.async.cg.shared.global [%0], [%1], 16;" :: "r"(saddr), "l"(ga));
}
#define CP_COMMIT() asm volatile("cp.async.commit_group;" ::: "memory")
#define CP_WAIT1()  asm volatile("cp.async.wait_group 1;"  ::: "memory")
#define LDMX4(r, addr)                                                            \
    asm volatile("ldmatrix.sync.aligned.m8n8.x4.shared.b16 {%0,%1,%2,%3}, [%4];"  \
        : "=r"((r)[0]), "=r"((r)[1]), "=r"((r)[2]), "=r"((r)[3]) : "r"(addr))
#define MMAB(d, a, b0, b1)                                                        \
    asm volatile("mma.sync.aligned.m16n8k16.row.col.f32.bf16.bf16.f32 "           \
        "{%0,%1,%2,%3}, {%4,%5,%6,%7}, {%8,%9}, {%0,%1,%2,%3};"                   \
        : "+f"((d)[0]), "+f"((d)[1]), "+f"((d)[2]), "+f"((d)[3])                  \
        : "r"((a)[0]), "r"((a)[1]), "r"((a)[2]), "r"((a)[3]), "r"(b0), "r"(b1))
#define MMAH(d, a, b0, b1)                                                        \
    asm volatile("mma.sync.aligned.m16n8k16.row.col.f32.f16.f16.f32 "             \
        "{%0,%1,%2,%3}, {%4,%5,%6,%7}, {%8,%9}, {%0,%1,%2,%3};"                   \
        : "+f"((d)[0]), "+f"((d)[1]), "+f"((d)[2]), "+f"((d)[3])                  \
        : "r"((a)[0]), "r"((a)[1]), "r"((a)[2]), "r"((a)[3]), "r"(b0), "r"(b1))

// ---------------------------------------------------------------------------
// Shared GEMM config: CTA 128x256, BK=32, 512 threads (16 warps, 4x4),
// warp tile 32x64. Smem rows: 32 elems (64B) padded to 80B stride.
// Split-bf16 GEMM buffer: Ah | Al | Bh | Bl
// ---------------------------------------------------------------------------
#define BM 128
#define BN 256
#define BK 32
#define ROWB 80
#define A_PL   (BM * ROWB)                  // 10240
#define B_PL   (BN * ROWB)                  // 20480
#define BUF_BYTES (2 * A_PL + 2 * B_PL)     // 61440
#define GEMM_SMEM (3 * BUF_BYTES)           // 184320

__device__ __forceinline__ void load2(const __nv_bfloat16* __restrict__ Ah,
                                      const __nv_bfloat16* __restrict__ Al, int lda,
                                      const __nv_bfloat16* __restrict__ Bh,
                                      const __nv_bfloat16* __restrict__ Bl, int ldb,
                                      uint32_t sbase, int tid) {
    {
        int row = tid >> 2, q = tid & 3;
        uint32_t d = sbase + (uint32_t)(row * ROWB + q * 16);
        cp16(d,        Ah + (size_t)row * lda + q * 8);
        cp16(d + A_PL, Al + (size_t)row * lda + q * 8);
    }
    #pragma unroll
    for (int i = 0; i < 2; i++) {
        int t = i * 512 + tid;
        int row = t >> 2, q = t & 3;
        uint32_t d = sbase + 2 * A_PL + (uint32_t)(row * ROWB + q * 16);
        cp16(d,        Bh + (size_t)row * ldb + q * 8);
        cp16(d + B_PL, Bl + (size_t)row * ldb + q * 8);
    }
}

__device__ __forceinline__ void compute2(uint32_t sa, int lane, int wm, int wn,
                                         float (&acc)[2][8][4]) {
    const int arow = (lane & 15);
    const int akb  = ((lane >> 4) & 1) * 16;
    const int brow = (lane & 7) + ((lane >> 4) & 1) * 8;
    const int bkb  = ((lane >> 3) & 1) * 16;
    #pragma unroll
    for (int ks = 0; ks < 2; ks++) {
        uint32_t ah[2][4], al[2][4];
        #pragma unroll
        for (int mt = 0; mt < 2; mt++) {
            uint32_t ad = sa + (uint32_t)((wm * 32 + mt * 16 + arow) * ROWB + akb + ks * 32);
            LDMX4(ah[mt], ad);
            LDMX4(al[mt], ad + A_PL);
        }
        #pragma unroll
        for (int np = 0; np < 4; np++) {
            uint32_t bd = sa + 2 * A_PL +
                (uint32_t)((wn * 64 + np * 16 + brow) * ROWB + bkb + ks * 32);
            uint32_t bh[4], bl[4];
            LDMX4(bh, bd);
            LDMX4(bl, bd + B_PL);
            #pragma unroll
            for (int h = 0; h < 2; h++) {
                #pragma unroll
                for (int mt = 0; mt < 2; mt++) {
                    MMAB(acc[mt][np * 2 + h], ah[mt], bh[2 * h], bh[2 * h + 1]);
                    MMAB(acc[mt][np * 2 + h], ah[mt], bl[2 * h], bl[2 * h + 1]);
                    MMAB(acc[mt][np * 2 + h], al[mt], bh[2 * h], bh[2 * h + 1]);
                }
            }
        }
    }
}

// MODE: 0 = fp32 out; 1 = bf16 hi/lo planes + bias[col]; 2 = fp16 hi/lo planes + bias[row]
template<int MODE>
__global__ __launch_bounds__(512)
void gemm512(const __nv_bfloat16* __restrict__ Ah, const __nv_bfloat16* __restrict__ Al,
             int lda, size_t sA,
             const __nv_bfloat16* __restrict__ Bh, const __nv_bfloat16* __restrict__ Bl,
             int ldb, size_t sB,
             void* __restrict__ D0, void* __restrict__ D1, int ldd, size_t sD,
             const float* __restrict__ bias, int K)
{
    extern __shared__ __align__(16) uint32_t smraw[];
    const uint32_t smbase = smem_u32(smraw);
    const int tid = threadIdx.x;
    const int lane = tid & 31, wid = tid >> 5;
    const int wm = wid >> 2, wn = wid & 3;
    const int z = blockIdx.z;
    const int bm = blockIdx.y * BM, bn = blockIdx.x * BN;

    Ah += (size_t)z * sA + (size_t)bm * lda;
    Al += (size_t)z * sA + (size_t)bm * lda;
    Bh += (size_t)z * sB + (size_t)bn * ldb;
    Bl += (size_t)z * sB + (size_t)bn * ldb;

    float acc[2][8][4];
    #pragma unroll
    for (int i = 0; i < 2; i++)
        #pragma unroll
        for (int j = 0; j < 8; j++)
            #pragma unroll
            for (int v = 0; v < 4; v++) acc[i][j][v] = 0.f;

    const int S = K / BK;
    load2(Ah, Al, lda, Bh, Bl, ldb, smbase, tid);
    CP_COMMIT();
    load2(Ah + BK, Al + BK, lda, Bh + BK, Bl + BK, ldb, smbase + BUF_BYTES, tid);
    CP_COMMIT();

    #pragma unroll 1
    for (int s = 0; s < S; s++) {
        CP_WAIT1();
        __syncthreads();
        if (s + 2 < S)
            load2(Ah + (s + 2) * BK, Al + (s + 2) * BK, lda,
                  Bh + (s + 2) * BK, Bl + (s + 2) * BK, ldb,
                  smbase + (uint32_t)((s + 2) % 3) * BUF_BYTES, tid);
        CP_COMMIT();
        compute2(smbase + (uint32_t)(s % 3) * BUF_BYTES, lane, wm, wn, acc);
    }

    #pragma unroll
    for (int nt = 0; nt < 8; nt++) {
        int col = bn + wn * 64 + nt * 8 + (lane & 3) * 2;
        float bc0 = 0.f, bc1 = 0.f;
        if (MODE == 1) { bc0 = bias[col]; bc1 = bias[col + 1]; }
        #pragma unroll
        for (int mt = 0; mt < 2; mt++) {
            int r0 = bm + wm * 32 + mt * 16 + (lane >> 2);
            if (MODE == 0) {
                float* D = (float*)D0 + (size_t)z * sD;
                *(float2*)&D[(size_t)r0 * ldd + col] =
                    make_float2(acc[mt][nt][0], acc[mt][nt][1]);
                *(float2*)&D[(size_t)(r0 + 8) * ldd + col] =
                    make_float2(acc[mt][nt][2], acc[mt][nt][3]);
            } else if (MODE == 1) {
                float v0 = acc[mt][nt][0] + bc0, v1 = acc[mt][nt][1] + bc1;
                float v2 = acc[mt][nt][2] + bc0, v3 = acc[mt][nt][3] + bc1;
                __nv_bfloat16 h0 = __float2bfloat16(v0), h1 = __float2bfloat16(v1);
                __nv_bfloat16 h2 = __float2bfloat16(v2), h3 = __float2bfloat16(v3);
                __nv_bfloat16 l0 = __float2bfloat16(v0 - __bfloat162float(h0));
                __nv_bfloat16 l1 = __float2bfloat16(v1 - __bfloat162float(h1));
                __nv_bfloat16 l2 = __float2bfloat16(v2 - __bfloat162float(h2));
                __nv_bfloat16 l3 = __float2bfloat16(v3 - __bfloat162float(h3));
                uint32_t* Dh = (uint32_t*)((__nv_bfloat16*)D0 + (size_t)z * sD);
                uint32_t* Dl = (uint32_t*)((__nv_bfloat16*)D1 + (size_t)z * sD);
                size_t o0 = ((size_t)r0 * ldd + col) >> 1;
                size_t o1 = ((size_t)(r0 + 8) * ldd + col) >> 1;
                Dh[o0] = (uint32_t)__bfloat16_as_ushort(h0) |
                         ((uint32_t)__bfloat16_as_ushort(h1) << 16);
                Dh[o1] = (uint32_t)__bfloat16_as_ushort(h2) |
                         ((uint32_t)__bfloat16_as_ushort(h3) << 16);
                Dl[o0] = (uint32_t)__bfloat16_as_ushort(l0) |
                         ((uint32_t)__bfloat16_as_ushort(l1) << 16);
                Dl[o1] = (uint32_t)__bfloat16_as_ushort(l2) |
                         ((uint32_t)__bfloat16_as_ushort(l3) << 16);
            } else {
                float b0 = bias[r0], b8 = bias[r0 + 8];
                float v0 = acc[mt][nt][0] + b0, v1 = acc[mt][nt][1] + b0;
                float v2 = acc[mt][nt][2] + b8, v3 = acc[mt][nt][3] + b8;
                __half h0 = __float2half(v0), h1 = __float2half(v1);
                __half h2 = __float2half(v2), h3 = __float2half(v3);
                __half l0 = __float2half(v0 - __half2float(h0));
                __half l1 = __float2half(v1 - __half2float(h1));
                __half l2 = __float2half(v2 - __half2float(h2));
                __half l3 = __float2half(v3 - __half2float(h3));
                uint32_t* Dh = (uint32_t*)((__half*)D0 + (size_t)z * sD);
                uint32_t* Dl = (uint32_t*)((__half*)D1 + (size_t)z * sD);
                size_t o0 = ((size_t)r0 * ldd + col) >> 1;
                size_t o1 = ((size_t)(r0 + 8) * ldd + col) >> 1;
                Dh[o0] = (uint32_t)__half_as_ushort(h0) | ((uint32_t)__half_as_ushort(h1) << 16);
                Dh[o1] = (uint32_t)__half_as_ushort(h2) | ((uint32_t)__half_as_ushort(h3) << 16);
                Dl[o0] = (uint32_t)__half_as_ushort(l0) | ((uint32_t)__half_as_ushort(l1) << 16);
                Dl[o1] = (uint32_t)__half_as_ushort(l2) | ((uint32_t)__half_as_ushort(l3) << 16);
            }
        }
    }
}

// ---------------------------------------------------------------------------
// AV GEMM: A = V fp16 hi/lo planes [c][j], B = attn fp16 [i][j]. 2-MMA emul.
// Buffer: Ah | Al | B
// ---------------------------------------------------------------------------
#define OBUF_BYTES (2 * A_PL + B_PL)       // 40960
#define OUT_SMEM   (3 * OBUF_BYTES)        // 122880

__device__ __forceinline__ void load_av(const __half* __restrict__ Ah,
                                        const __half* __restrict__ Al,
                                        const __half* __restrict__ B,
                                        uint32_t sbase, int tid) {
    {
        int row = tid >> 2, q = tid & 3;
        uint32_t d = sbase + (uint32_t)(row * ROWB + q * 16);
        cp16(d,        Ah + (size_t)row * NPIX + q * 8);
        cp16(d + A_PL, Al + (size_t)row * NPIX + q * 8);
    }
    #pragma unroll
    for (int i = 0; i < 2; i++) {
        int t = i * 512 + tid;
        int row = t >> 2, q = t & 3;
        cp16(sbase + 2 * A_PL + (uint32_t)(row * ROWB + q * 16),
             B + (size_t)row * NPIX + q * 8);
    }
}

__global__ __launch_bounds__(512)
void av_gemm512(const __half* __restrict__ Ah, const __half* __restrict__ Al,
                const __half* __restrict__ B, float* __restrict__ D)
{
    extern __shared__ __align__(16) uint32_t smraw[];
    const uint32_t smbase = smem_u32(smraw);
    const int tid = threadIdx.x;
    const int lane = tid & 31, wid = tid >> 5;
    const int wm = wid >> 2, wn = wid & 3;
    const int z = blockIdx.z;
    const int bm = blockIdx.y * BM, bn = blockIdx.x * BN;

    Ah += (size_t)z * CH * NPIX + (size_t)bm * NPIX;
    Al += (size_t)z * CH * NPIX + (size_t)bm * NPIX;
    B  += (size_t)z * NPIX * NPIX + (size_t)bn * NPIX;
    D  += (size_t)z * CH * NPIX;

    float acc[2][8][4];
    #pragma unroll
    for (int i = 0; i < 2; i++)
        #pragma unroll
        for (int j = 0; j < 8; j++)
            #pragma unroll
            for (int v = 0; v < 4; v++) acc[i][j][v] = 0.f;

    const int S = NPIX / BK;   // 128
    load_av(Ah, Al, B, smbase, tid);
    CP_COMMIT();
    load_av(Ah + BK, Al + BK, B + BK, smbase + OBUF_BYTES, tid);
    CP_COMMIT();

    const int arow = (lane & 15);
    const int akb  = ((lane >> 4) & 1) * 16;
    const int brow = (lane & 7) + ((lane >> 4) & 1) * 8;
    const int bkb  = ((lane >> 3) & 1) * 16;

    #pragma unroll 1
    for (int s = 0; s < S; s++) {
        CP_WAIT1();
        __syncthreads();
        if (s + 2 < S)
            load_av(Ah + (s + 2) * BK, Al + (s + 2) * BK, B + (s + 2) * BK,
                    smbase + (uint32_t)((s + 2) % 3) * OBUF_BYTES, tid);
        CP_COMMIT();

        uint32_t sa = smbase + (uint32_t)(s % 3) * OBUF_BYTES;
        #pragma unroll
        for (int ks = 0; ks < 2; ks++) {
            uint32_t ah[2][4], al[2][4];
            #pragma unroll
            for (int mt = 0; mt < 2; mt++) {
                uint32_t ad = sa + (uint32_t)((wm * 32 + mt * 16 + arow) * ROWB + akb + ks * 32);
                LDMX4(ah[mt], ad);
                LDMX4(al[mt], ad + A_PL);
            }
            #pragma unroll
            for (int np = 0; np < 4; np++) {
                uint32_t bd = sa + 2 * A_PL +
                    (uint32_t)((wn * 64 + np * 16 + brow) * ROWB + bkb + ks * 32);
                uint32_t bf[4];
                LDMX4(bf, bd);
                #pragma unroll
                for (int h = 0; h < 2; h++) {
                    #pragma unroll
                    for (int mt = 0; mt < 2; mt++) {
                        MMAH(acc[mt][np * 2 + h], ah[mt], bf[2 * h], bf[2 * h + 1]);
                        MMAH(acc[mt][np * 2 + h], al[mt], bf[2 * h], bf[2 * h + 1]);
                    }
                }
            }
        }
    }

    #pragma unroll
    for (int nt = 0; nt < 8; nt++) {
        int col = bn + wn * 64 + nt * 8 + (lane & 3) * 2;
        #pragma unroll
        for (int mt = 0; mt < 2; mt++) {
            int r0 = bm + wm * 32 + mt * 16 + (lane >> 2);
            *(float2*)&D[(size_t)r0 * NPIX + col] =
                make_float2(acc[mt][nt][0], acc[mt][nt][1]);
            *(float2*)&D[(size_t)(r0 + 8) * NPIX + col] =
                make_float2(acc[mt][nt][2], acc[mt][nt][3]);
        }
    }
}

// ---------------------------------------------------------------------------
// Packing kernels
// ---------------------------------------------------------------------------
__device__ __forceinline__ void split_bf(float v, __nv_bfloat16* H, __nv_bfloat16* L) {
    __nv_bfloat16 h = __float2bfloat16(v);
    *H = h;
    *L = __float2bfloat16(v - __bfloat162float(h));
}

__global__ __launch_bounds__(256) void pack_w_kernel(
    const float* __restrict__ wq, const float* __restrict__ wk,
    const float* __restrict__ wv)
{
    int i = blockIdx.x * 256 + threadIdx.x;
    split_bf(wq[i], &g_wh[i], &g_wl[i]);
    split_bf(wk[i], &g_wh[CH * CH + i], &g_wl[CH * CH + i]);
    split_bf(wv[i], &g_wh[2 * CH * CH + i], &g_wl[2 * CH * CH + i]);
}

__global__ __launch_bounds__(256) void pack_xt_kernel(const float* __restrict__ x)
{
    __shared__ float t[32][33];
    const int b = blockIdx.z;
    const int n0 = blockIdx.x * 32, c0 = blockIdx.y * 32;
    const int tx = threadIdx.x, ty = threadIdx.y;   // 32 x 8
    const float* xb = x + (size_t)b * CH * NPIX;
    #pragma unroll
    for (int i = 0; i < 4; i++)
        t[ty * 4 + i][tx] = xb[(size_t)(c0 + ty * 4 + i) * NPIX + n0 + tx];
    __syncthreads();
    size_t base = (size_t)b * NPIX * CH;
    #pragma unroll
    for (int i = 0; i < 4; i++) {
        size_t o = base + (size_t)(n0 + ty * 4 + i) * CH + c0 + tx;
        split_bf(t[tx][ty * 4 + i], &g_xth[o], &g_xtl[o]);
    }
}

// ---------------------------------------------------------------------------
// Softmax: fp32 scores -> fp16 attn
// ---------------------------------------------------------------------------
__global__ __launch_bounds__(256) void softmax_kernel()
{
    const float* row = g_s + (size_t)blockIdx.x * NPIX;
    __half* orow = g_ah + (size_t)blockIdx.x * NPIX;
    const int tid = threadIdx.x;

    float v[16];
    float mx = -1e30f;
    #pragma unroll
    for (int i = 0; i < 16; i++) {
        v[i] = row[tid + 256 * i];
        mx = fmaxf(mx, v[i]);
    }
    __shared__ float red[8];
    #pragma unroll
    for (int o = 16; o > 0; o >>= 1)
        mx = fmaxf(mx, __shfl_xor_sync(0xffffffffu, mx, o));
    if ((tid & 31) == 0) red[tid >> 5] = mx;
    __syncthreads();
    float bm = red[0];
    #pragma unroll
    for (int i = 1; i < 8; i++) bm = fmaxf(bm, red[i]);
    __syncthreads();

    float sum = 0.f;
    #pragma unroll
    for (int i = 0; i < 16; i++) {
        v[i] = expf(v[i] - bm);
        sum += v[i];
    }
    #pragma unroll
    for (int o = 16; o > 0; o >>= 1)
        sum += __shfl_xor_sync(0xffffffffu, sum, o);
    if ((tid & 31) == 0) red[tid >> 5] = sum;
    __syncthreads();
    float tot = 0.f;
    #pragma unroll
    for (int i = 0; i < 8; i++) tot += red[i];
    float inv = 1.0f / tot;

    #pragma unroll
    for (int i = 0; i < 16; i++)
        orow[tid + 256 * i] = __float2half(v[i] * inv);
}

// ---------------------------------------------------------------------------
extern "C" void kernel_launch(void* const* d_in, const int* in_sizes, int n_in,
                              void* d_out, int out_size)
{
    const float* x  = (const float*)d_in[0];
    const float* wq = (const float*)d_in[1];
    const float* bq = (const float*)d_in[2];
    const float* wk = (const float*)d_in[3];
    const float* bk = (const float*)d_in[4];
    const float* wv = (const float*)d_in[5];
    const float* bv = (const float*)d_in[6];
    float* out = (float*)d_out;

    void *pwh, *pwl, *pxth, *pxtl, *pqth, *pqtl, *pkth, *pktl, *pvph, *pvpl, *ps, *pah;
    cudaGetSymbolAddress(&pwh, g_wh);   cudaGetSymbolAddress(&pwl, g_wl);
    cudaGetSymbolAddress(&pxth, g_xth); cudaGetSymbolAddress(&pxtl, g_xtl);
    cudaGetSymbolAddress(&pqth, g_qth); cudaGetSymbolAddress(&pqtl, g_qtl);
    cudaGetSymbolAddress(&pkth, g_kth); cudaGetSymbolAddress(&pktl, g_ktl);
    cudaGetSymbolAddress(&pvph, g_vph); cudaGetSymbolAddress(&pvpl, g_vpl);
    cudaGetSymbolAddress(&ps, g_s);     cudaGetSymbolAddress(&pah, g_ah);
    __nv_bfloat16* wh  = (__nv_bfloat16*)pwh;
    __nv_bfloat16* wl  = (__nv_bfloat16*)pwl;
    __nv_bfloat16* xth = (__nv_bfloat16*)pxth;
    __nv_bfloat16* xtl = (__nv_bfloat16*)pxtl;
    __nv_bfloat16* qth = (__nv_bfloat16*)pqth;
    __nv_bfloat16* qtl = (__nv_bfloat16*)pqtl;
    __nv_bfloat16* kth = (__nv_bfloat16*)pkth;
    __nv_bfloat16* ktl = (__nv_bfloat16*)pktl;
    __half* vph = (__half*)pvph;
    __half* vpl = (__half*)pvpl;
    float*  sc  = (float*)ps;
    __half* ah  = (__half*)pah;

    cudaFuncSetAttribute(gemm512<0>, cudaFuncAttributeMaxDynamicSharedMemorySize, GEMM_SMEM);
    cudaFuncSetAttribute(gemm512<1>, cudaFuncAttributeMaxDynamicSharedMemorySize, GEMM_SMEM);
    cudaFuncSetAttribute(gemm512<2>, cudaFuncAttributeMaxDynamicSharedMemorySize, GEMM_SMEM);
    cudaFuncSetAttribute(av_gemm512, cudaFuncAttributeMaxDynamicSharedMemorySize, OUT_SMEM);

    pack_w_kernel<<<CH * CH / 256, 256>>>(wq, wk, wv);
    pack_xt_kernel<<<dim3(NPIX / 32, CH / 32, BATCH), dim3(32, 8)>>>(x);

    // Q^T[n][c] = X^T[n][k] * Wq[c][k]^T + bq (col bias)
    gemm512<1><<<dim3(1, 32, BATCH), 512, GEMM_SMEM>>>(
        xth, xtl, CH, (size_t)NPIX * CH, wh, wl, CH, 0,
        qth, qtl, CH, (size_t)NPIX * CH, bq, CH);
    gemm512<1><<<dim3(1, 32, BATCH), 512, GEMM_SMEM>>>(
        xth, xtl, CH, (size_t)NPIX * CH, wh + CH * CH, wl + CH * CH, CH, 0,
        kth, ktl, CH, (size_t)NPIX * CH, bk, CH);
    // V[c][n] = Wv[c][k] * X^T[n][k]^T + bv (row bias) -> fp16 planes
    gemm512<2><<<dim3(NPIX / BN, CH / BM, BATCH), 512, GEMM_SMEM>>>(
        wh + 2 * CH * CH, wl + 2 * CH * CH, CH, 0,
        xth, xtl, CH, (size_t)NPIX * CH,
        vph, vpl, NPIX, (size_t)CH * NPIX, bv, CH);
    // scores[i][j] = Q^T[i][k] * K^T[j][k]^T
    gemm512<0><<<dim3(NPIX / BN, NPIX / BM, BATCH), 512, GEMM_SMEM>>>(
        qth, qtl, CH, (size_t)NPIX * CH, kth, ktl, CH, (size_t)NPIX * CH,
        sc, nullptr, NPIX, (size_t)NPIX * NPIX, nullptr, CH);
    softmax_kernel<<<BATCH * NPIX, 256>>>();
    // out[c][i] = V[c][j] * attn[i][j]^T
    av_gemm512<<<dim3(NPIX / BN, CH / BM, BATCH), 512, OUT_SMEM>>>(vph, vpl, ah, out);
}

// round 6
// speedup vs baseline: 1.0610x; 1.0610x over previous
#include <cuda_runtime.h>
#include <cuda_bf16.h>
#include <cuda_fp16.h>
#include <math.h>
#include <stdint.h>

#define BATCH 8
#define CH    256
#define NPIX  4096

// Packed split formats: u32 = lo16(hi) | lo16(lo)<<16, value ~= hi + lo
static __device__ uint32_t g_wp[3 * CH * CH];                  // packed bf16 wq|wk|wv
static __device__ uint32_t g_xt[(size_t)BATCH * NPIX * CH];    // x^T  [b][n][c] bf16-split
static __device__ uint32_t g_qt[(size_t)BATCH * NPIX * CH];    // Q^T  [b][n][c] bf16-split
static __device__ uint32_t g_kt[(size_t)BATCH * NPIX * CH];    // K^T  [b][n][c] bf16-split
static __device__ uint32_t g_vp[(size_t)BATCH * CH * NPIX];    // V    [b][c][n] fp16-split
static __device__ float    g_s [(size_t)BATCH * NPIX * NPIX];  // scores fp32
static __device__ __half   g_ah[(size_t)BATCH * NPIX * NPIX];  // attn fp16 [b][i][j]

__device__ __forceinline__ uint32_t smem_u32(const void* p) {
    uint32_t a;
    asm("{ .reg .u64 t; cvta.to.shared.u64 t, %1; cvt.u32.u64 %0, t; }" : "=r"(a) : "l"(p));
    return a;
}
__device__ __forceinline__ uint32_t pack_split(float v) {         // bf16 hi+lo
    __nv_bfloat16 h = __float2bfloat16(v);
    float r = v - __bfloat162float(h);
    __nv_bfloat16 l = __float2bfloat16(r);
    return (uint32_t)__bfloat16_as_ushort(h) | ((uint32_t)__bfloat16_as_ushort(l) << 16);
}
__device__ __forceinline__ uint32_t pack_split_h(float v) {       // fp16 hi+lo
    __half h = __float2half(v);
    float r = v - __half2float(h);
    __half l = __float2half(r);
    return (uint32_t)__half_as_ushort(h) | ((uint32_t)__half_as_ushort(l) << 16);
}
__device__ __forceinline__ void cp16(uint32_t saddr, const void* g) {
    uint64_t ga;
    asm("cvta.to.global.u64 %0, %1;" : "=l"(ga) : "l"(g));
    asm volatile("cp.async.cg.shared.global [%0], [%1], 16;" :: "r"(saddr), "l"(ga));
}
#define CP_COMMIT() asm volatile("cp.async.commit_group;" ::: "memory")
#define CP_WAIT1()  asm volatile("cp.async.wait_group 1;"  ::: "memory")
#define LDS64(a, b, addr) \
    asm volatile("ld.shared.v2.u32 {%0,%1}, [%2];" : "=r"(a), "=r"(b) : "r"(addr))
#define LDS32(a, addr) \
    asm volatile("ld.shared.u32 %0, [%1];" : "=r"(a) : "r"(addr))
#define MMAB(d, a, b0, b1)                                                        \
    asm volatile("mma.sync.aligned.m16n8k16.row.col.f32.bf16.bf16.f32 "           \
        "{%0,%1,%2,%3}, {%4,%5,%6,%7}, {%8,%9}, {%0,%1,%2,%3};"                   \
        : "+f"((d)[0]), "+f"((d)[1]), "+f"((d)[2]), "+f"((d)[3])                  \
        : "r"((a)[0]), "r"((a)[1]), "r"((a)[2]), "r"((a)[3]), "r"(b0), "r"(b1))
#define MMAH(d, a, b0, b1)                                                        \
    asm volatile("mma.sync.aligned.m16n8k16.row.col.f32.f16.f16.f32 "             \
        "{%0,%1,%2,%3}, {%4,%5,%6,%7}, {%8,%9}, {%0,%1,%2,%3};"                   \
        : "+f"((d)[0]), "+f"((d)[1]), "+f"((d)[2]), "+f"((d)[3])                  \
        : "r"((a)[0]), "r"((a)[1]), "r"((a)[2]), "r"((a)[3]), "r"(b0), "r"(b1))

// ---------------------------------------------------------------------------
// GEMM A: packed split-bf16 both operands, 3-MMA emulation, pass-major order.
// D[M,N] = A[M,K] * B[N,K]^T. CTA 128x256, BK=32, 8 warps, 3-stage cp.async.
// MODE: 0 = fp32 out; 1 = packed bf16-split out + bias[col];
//       2 = packed fp16-split out + bias[row]
// ---------------------------------------------------------------------------
#define BM 128
#define BN 256
#define BK 32
#define A_U32S  (BM * 40)
#define B_U32S  (BN * 40)
#define A_BYTES (A_U32S * 4)
#define BUF_BYTES ((A_U32S + B_U32S) * 4)   // 61440
#define GEMM_SMEM (3 * BUF_BYTES)           // 184320

__device__ __forceinline__ void load_tiles(const uint32_t* __restrict__ Ag, int lda,
                                           const uint32_t* __restrict__ Bg, int ldb,
                                           uint32_t sbase, int tid) {
    #pragma unroll
    for (int i = 0; i < 4; i++) {
        int t = i * 256 + tid;
        int row = t >> 3, q = t & 7;
        cp16(sbase + (uint32_t)(row * 40 + q * 4) * 4, Ag + (size_t)row * lda + q * 4);
    }
    #pragma unroll
    for (int i = 0; i < 8; i++) {
        int t = i * 256 + tid;
        int row = t >> 3, q = t & 7;
        cp16(sbase + A_BYTES + (uint32_t)(row * 40 + q * 4) * 4, Bg + (size_t)row * ldb + q * 4);
    }
}

__device__ __forceinline__ void compute_tile(uint32_t sa, int lane, int wm, int wn,
                                             float (&acc)[4][8][4]) {
    uint32_t sb = sa + A_BYTES;
    #pragma unroll
    for (int ks = 0; ks < 2; ks++) {
        const int kc = ks * 16 + (lane & 3) * 2;
        uint32_t ah[4][4], al[4][4];
        #pragma unroll
        for (int mt = 0; mt < 4; mt++) {
            int r = wm * 64 + mt * 16 + (lane >> 2);
            uint32_t x0, x1, y0, y1, x2, x3, y2, y3;
            LDS64(x0, x1, sa + (uint32_t)(r * 40 + kc) * 4);
            LDS64(y0, y1, sa + (uint32_t)((r + 8) * 40 + kc) * 4);
            LDS64(x2, x3, sa + (uint32_t)(r * 40 + kc + 8) * 4);
            LDS64(y2, y3, sa + (uint32_t)((r + 8) * 40 + kc + 8) * 4);
            ah[mt][0] = __byte_perm(x0, x1, 0x5410); al[mt][0] = __byte_perm(x0, x1, 0x7632);
            ah[mt][1] = __byte_perm(y0, y1, 0x5410); al[mt][1] = __byte_perm(y0, y1, 0x7632);
            ah[mt][2] = __byte_perm(x2, x3, 0x5410); al[mt][2] = __byte_perm(x2, x3, 0x7632);
            ah[mt][3] = __byte_perm(y2, y3, 0x5410); al[mt][3] = __byte_perm(y2, y3, 0x7632);
        }
        #pragma unroll
        for (int nt = 0; nt < 8; nt++) {
            int r = wn * 64 + nt * 8 + (lane >> 2);
            uint32_t u0, u1, u2, u3;
            LDS64(u0, u1, sb + (uint32_t)(r * 40 + kc) * 4);
            LDS64(u2, u3, sb + (uint32_t)(r * 40 + kc + 8) * 4);
            uint32_t bh0 = __byte_perm(u0, u1, 0x5410), bh1 = __byte_perm(u2, u3, 0x5410);
            uint32_t bl0 = __byte_perm(u0, u1, 0x7632), bl1 = __byte_perm(u2, u3, 0x7632);
            // Pass-major: same-accumulator reuse distance = 4 independent MMAs
            #pragma unroll
            for (int mt = 0; mt < 4; mt++) MMAB(acc[mt][nt], ah[mt], bh0, bh1);
            #pragma unroll
            for (int mt = 0; mt < 4; mt++) MMAB(acc[mt][nt], ah[mt], bl0, bl1);
            #pragma unroll
            for (int mt = 0; mt < 4; mt++) MMAB(acc[mt][nt], al[mt], bh0, bh1);
        }
    }
}

template<int MODE>
__global__ __launch_bounds__(256)
void gemm_kernel(const uint32_t* __restrict__ A, int lda, size_t sA,
                 const uint32_t* __restrict__ B, int ldb, size_t sB,
                 void* __restrict__ Dv, int ldd, size_t sD,
                 const float* __restrict__ bias, int K)
{
    extern __shared__ __align__(16) uint32_t smraw[];
    const uint32_t smbase = smem_u32(smraw);
    const int tid = threadIdx.x;
    const int lane = tid & 31, wid = tid >> 5;
    const int wm = wid >> 2, wn = wid & 3;
    const int z = blockIdx.z;
    const int bm = blockIdx.y * BM, bn = blockIdx.x * BN;

    A += (size_t)z * sA + (size_t)bm * lda;
    B += (size_t)z * sB + (size_t)bn * ldb;

    float acc[4][8][4];
    #pragma unroll
    for (int i = 0; i < 4; i++)
        #pragma unroll
        for (int j = 0; j < 8; j++)
            #pragma unroll
            for (int v = 0; v < 4; v++) acc[i][j][v] = 0.f;

    const int S = K / BK;
    load_tiles(A, lda, B, ldb, smbase, tid);
    CP_COMMIT();
    load_tiles(A + BK, lda, B + BK, ldb, smbase + BUF_BYTES, tid);
    CP_COMMIT();

    #pragma unroll 1
    for (int s = 0; s < S; s++) {
        CP_WAIT1();
        __syncthreads();
        if (s + 2 < S)
            load_tiles(A + (s + 2) * BK, lda, B + (s + 2) * BK, ldb,
                       smbase + (uint32_t)((s + 2) % 3) * BUF_BYTES, tid);
        CP_COMMIT();
        compute_tile(smbase + (uint32_t)(s % 3) * BUF_BYTES, lane, wm, wn, acc);
    }

    #pragma unroll
    for (int nt = 0; nt < 8; nt++) {
        int col = bn + wn * 64 + nt * 8 + (lane & 3) * 2;
        float bc0 = 0.f, bc1 = 0.f;
        if (MODE == 1) { bc0 = bias[col]; bc1 = bias[col + 1]; }
        #pragma unroll
        for (int mt = 0; mt < 4; mt++) {
            int r0 = bm + wm * 64 + mt * 16 + (lane >> 2);
            if (MODE == 0) {
                float* D = (float*)Dv + (size_t)z * sD;
                *(float2*)&D[(size_t)r0 * ldd + col] =
                    make_float2(acc[mt][nt][0], acc[mt][nt][1]);
                *(float2*)&D[(size_t)(r0 + 8) * ldd + col] =
                    make_float2(acc[mt][nt][2], acc[mt][nt][3]);
            } else {
                uint32_t* D = (uint32_t*)Dv + (size_t)z * sD;
                float br0 = bc0, br1 = bc1, br2 = bc0, br3 = bc1;
                if (MODE == 2) {
                    float b0 = bias[r0], b8 = bias[r0 + 8];
                    br0 = b0; br1 = b0; br2 = b8; br3 = b8;
                }
                uint32_t p0, p1, p2, p3;
                if (MODE == 2) {
                    p0 = pack_split_h(acc[mt][nt][0] + br0);
                    p1 = pack_split_h(acc[mt][nt][1] + br1);
                    p2 = pack_split_h(acc[mt][nt][2] + br2);
                    p3 = pack_split_h(acc[mt][nt][3] + br3);
                } else {
                    p0 = pack_split(acc[mt][nt][0] + br0);
                    p1 = pack_split(acc[mt][nt][1] + br1);
                    p2 = pack_split(acc[mt][nt][2] + br2);
                    p3 = pack_split(acc[mt][nt][3] + br3);
                }
                *(uint2*)&D[(size_t)r0 * ldd + col] = make_uint2(p0, p1);
                *(uint2*)&D[(size_t)(r0 + 8) * ldd + col] = make_uint2(p2, p3);
            }
        }
    }
}

// ---------------------------------------------------------------------------
// GEMM B (AV): A = V packed split-fp16 [c][j], B = attn fp16 [i][j].
// D[c][i] fp32. 2-MMA emulation, pass-major. CTA 128x256, BK=32, 3-stage.
// ---------------------------------------------------------------------------
#define OA_BYTES  (BM * 40 * 4)             // 20480
#define OB_BYTES  (BN * 20 * 4)             // 20480
#define OBUF_BYTES (OA_BYTES + OB_BYTES)    // 40960
#define OUT_SMEM  (3 * OBUF_BYTES)          // 122880

__device__ __forceinline__ void load_tiles_av(const uint32_t* __restrict__ Ag, int lda,
                                              const __half* __restrict__ Bg, int ldb,
                                              uint32_t sbase, int tid) {
    #pragma unroll
    for (int i = 0; i < 4; i++) {
        int t = i * 256 + tid;
        int row = t >> 3, q = t & 7;
        cp16(sbase + (uint32_t)(row * 40 + q * 4) * 4, Ag + (size_t)row * lda + q * 4);
    }
    #pragma unroll
    for (int i = 0; i < 4; i++) {
        int t = i * 256 + tid;
        int row = t >> 2, q = t & 3;
        cp16(sbase + OA_BYTES + (uint32_t)(row * 20 + q * 4) * 4,
             Bg + (size_t)row * ldb + q * 8);
    }
}

__global__ __launch_bounds__(256)
void av_gemm_kernel(const uint32_t* __restrict__ A,   // g_vp
                    const __half* __restrict__ B,      // g_ah
                    float* __restrict__ D)             // out
{
    extern __shared__ __align__(16) uint32_t smraw[];
    const uint32_t smbase = smem_u32(smraw);
    const int tid = threadIdx.x;
    const int lane = tid & 31, wid = tid >> 5;
    const int wm = wid >> 2, wn = wid & 3;
    const int z = blockIdx.z;
    const int bm = blockIdx.y * BM, bn = blockIdx.x * BN;

    A += (size_t)z * CH * NPIX + (size_t)bm * NPIX;
    B += (size_t)z * NPIX * NPIX + (size_t)bn * NPIX;
    D += (size_t)z * CH * NPIX;

    float acc[4][8][4];
    #pragma unroll
    for (int i = 0; i < 4; i++)
        #pragma unroll
        for (int j = 0; j < 8; j++)
            #pragma unroll
            for (int v = 0; v < 4; v++) acc[i][j][v] = 0.f;

    const int S = NPIX / BK;   // 128
    load_tiles_av(A, NPIX, B, NPIX, smbase, tid);
    CP_COMMIT();
    load_tiles_av(A + BK, NPIX, B + BK, NPIX, smbase + OBUF_BYTES, tid);
    CP_COMMIT();

    #pragma unroll 1
    for (int s = 0; s < S; s++) {
        CP_WAIT1();
        __syncthreads();
        if (s + 2 < S)
            load_tiles_av(A + (s + 2) * BK, NPIX, B + (s + 2) * BK, NPIX,
                          smbase + (uint32_t)((s + 2) % 3) * OBUF_BYTES, tid);
        CP_COMMIT();

        uint32_t sa = smbase + (uint32_t)(s % 3) * OBUF_BYTES;
        uint32_t sb = sa + OA_BYTES;
        #pragma unroll
        for (int ks = 0; ks < 2; ks++) {
            const int kc = ks * 16 + (lane & 3) * 2;   // u32 col in A tile
            uint32_t ah[4][4], al[4][4];
            #pragma unroll
            for (int mt = 0; mt < 4; mt++) {
                int r = wm * 64 + mt * 16 + (lane >> 2);
                uint32_t x0, x1, y0, y1, x2, x3, y2, y3;
                LDS64(x0, x1, sa + (uint32_t)(r * 40 + kc) * 4);
                LDS64(y0, y1, sa + (uint32_t)((r + 8) * 40 + kc) * 4);
                LDS64(x2, x3, sa + (uint32_t)(r * 40 + kc + 8) * 4);
                LDS64(y2, y3, sa + (uint32_t)((r + 8) * 40 + kc + 8) * 4);
                ah[mt][0] = __byte_perm(x0, x1, 0x5410); al[mt][0] = __byte_perm(x0, x1, 0x7632);
                ah[mt][1] = __byte_perm(y0, y1, 0x5410); al[mt][1] = __byte_perm(y0, y1, 0x7632);
                ah[mt][2] = __byte_perm(x2, x3, 0x5410); al[mt][2] = __byte_perm(x2, x3, 0x7632);
                ah[mt][3] = __byte_perm(y2, y3, 0x5410); al[mt][3] = __byte_perm(y2, y3, 0x7632);
            }
            const int bkc = ks * 8 + (lane & 3);       // u32 col in B tile (fp16 pairs)
            #pragma unroll
            for (int nt = 0; nt < 8; nt++) {
                int r = wn * 64 + nt * 8 + (lane >> 2);
                uint32_t b0, b1;
                LDS32(b0, sb + (uint32_t)(r * 20 + bkc) * 4);
                LDS32(b1, sb + (uint32_t)(r * 20 + bkc + 4) * 4);
                // Pass-major: reuse distance 4
                #pragma unroll
                for (int mt = 0; mt < 4; mt++) MMAH(acc[mt][nt], ah[mt], b0, b1);
                #pragma unroll
                for (int mt = 0; mt < 4; mt++) MMAH(acc[mt][nt], al[mt], b0, b1);
            }
        }
    }

    #pragma unroll
    for (int nt = 0; nt < 8; nt++) {
        int col = bn + wn * 64 + nt * 8 + (lane & 3) * 2;
        #pragma unroll
        for (int mt = 0; mt < 4; mt++) {
            int r0 = bm + wm * 64 + mt * 16 + (lane >> 2);
            *(float2*)&D[(size_t)r0 * NPIX + col] =
                make_float2(acc[mt][nt][0], acc[mt][nt][1]);
            *(float2*)&D[(size_t)(r0 + 8) * NPIX + col] =
                make_float2(acc[mt][nt][2], acc[mt][nt][3]);
        }
    }
}

// ---------------------------------------------------------------------------
// Packing kernels
// ---------------------------------------------------------------------------
__global__ __launch_bounds__(256) void pack_w_kernel(
    const float* __restrict__ wq, const float* __restrict__ wk,
    const float* __restrict__ wv)
{
    int i = blockIdx.x * 256 + threadIdx.x;
    g_wp[i]               = pack_split(wq[i]);
    g_wp[CH * CH + i]     = pack_split(wk[i]);
    g_wp[2 * CH * CH + i] = pack_split(wv[i]);
}

__global__ __launch_bounds__(256) void pack_xt_kernel(const float* __restrict__ x)
{
    __shared__ float t[32][33];
    const int b = blockIdx.z;
    const int n0 = blockIdx.x * 32, c0 = blockIdx.y * 32;
    const int tx = threadIdx.x, ty = threadIdx.y;   // 32 x 8
    const float* xb = x + (size_t)b * CH * NPIX;
    #pragma unroll
    for (int i = 0; i < 4; i++)
        t[ty * 4 + i][tx] = xb[(size_t)(c0 + ty * 4 + i) * NPIX + n0 + tx];
    __syncthreads();
    uint32_t* xt = g_xt + (size_t)b * NPIX * CH;
    #pragma unroll
    for (int i = 0; i < 4; i++)
        xt[(size_t)(n0 + ty * 4 + i) * CH + c0 + tx] = pack_split(t[tx][ty * 4 + i]);
}

// ---------------------------------------------------------------------------
// Softmax: fp32 scores -> fp16 attn
// ---------------------------------------------------------------------------
__global__ __launch_bounds__(256) void softmax_kernel()
{
    const float* row = g_s + (size_t)blockIdx.x * NPIX;
    __half* orow = g_ah + (size_t)blockIdx.x * NPIX;
    const int tid = threadIdx.x;

    float v[16];
    float mx = -1e30f;
    #pragma unroll
    for (int i = 0; i < 16; i++) {
        v[i] = row[tid + 256 * i];
        mx = fmaxf(mx, v[i]);
    }
    __shared__ float red[8];
    #pragma unroll
    for (int o = 16; o > 0; o >>= 1)
        mx = fmaxf(mx, __shfl_xor_sync(0xffffffffu, mx, o));
    if ((tid & 31) == 0) red[tid >> 5] = mx;
    __syncthreads();
    float bm = red[0];
    #pragma unroll
    for (int i = 1; i < 8; i++) bm = fmaxf(bm, red[i]);
    __syncthreads();

    float sum = 0.f;
    #pragma unroll
    for (int i = 0; i < 16; i++) {
        v[i] = expf(v[i] - bm);
        sum += v[i];
    }
    #pragma unroll
    for (int o = 16; o > 0; o >>= 1)
        sum += __shfl_xor_sync(0xffffffffu, sum, o);
    if ((tid & 31) == 0) red[tid >> 5] = sum;
    __syncthreads();
    float tot = 0.f;
    #pragma unroll
    for (int i = 0; i < 8; i++) tot += red[i];
    float inv = 1.0f / tot;

    #pragma unroll
    for (int i = 0; i < 16; i++)
        orow[tid + 256 * i] = __float2half(v[i] * inv);
}

// ---------------------------------------------------------------------------
extern "C" void kernel_launch(void* const* d_in, const int* in_sizes, int n_in,
                              void* d_out, int out_size)
{
    const float* x  = (const float*)d_in[0];
    const float* wq = (const float*)d_in[1];
    const float* bq = (const float*)d_in[2];
    const float* wk = (const float*)d_in[3];
    const float* bk = (const float*)d_in[4];
    const float* wv = (const float*)d_in[5];
    const float* bv = (const float*)d_in[6];
    float* out = (float*)d_out;

    void *pwp, *pxt, *pqt, *pkt, *pvp, *ps, *pah;
    cudaGetSymbolAddress(&pwp, g_wp);
    cudaGetSymbolAddress(&pxt, g_xt);
    cudaGetSymbolAddress(&pqt, g_qt);
    cudaGetSymbolAddress(&pkt, g_kt);
    cudaGetSymbolAddress(&pvp, g_vp);
    cudaGetSymbolAddress(&ps,  g_s);
    cudaGetSymbolAddress(&pah, g_ah);
    uint32_t* wp = (uint32_t*)pwp;
    uint32_t* xt = (uint32_t*)pxt;
    uint32_t* qt = (uint32_t*)pqt;
    uint32_t* kt = (uint32_t*)pkt;
    uint32_t* vp = (uint32_t*)pvp;
    float*    sc = (float*)ps;
    __half*   ah = (__half*)pah;

    cudaFuncSetAttribute(gemm_kernel<0>, cudaFuncAttributeMaxDynamicSharedMemorySize, GEMM_SMEM);
    cudaFuncSetAttribute(gemm_kernel<1>, cudaFuncAttributeMaxDynamicSharedMemorySize, GEMM_SMEM);
    cudaFuncSetAttribute(gemm_kernel<2>, cudaFuncAttributeMaxDynamicSharedMemorySize, GEMM_SMEM);
    cudaFuncSetAttribute(av_gemm_kernel, cudaFuncAttributeMaxDynamicSharedMemorySize, OUT_SMEM);

    pack_w_kernel<<<CH * CH / 256, 256>>>(wq, wk, wv);
    pack_xt_kernel<<<dim3(NPIX / 32, CH / 32, BATCH), dim3(32, 8)>>>(x);

    // Q^T[n][c] = X^T[n][k] * Wq[c][k]^T + bq (col bias)
    gemm_kernel<1><<<dim3(1, 32, BATCH), 256, GEMM_SMEM>>>(
        xt, CH, (size_t)NPIX * CH, wp, CH, 0,
        qt, CH, (size_t)NPIX * CH, bq, CH);
    gemm_kernel<1><<<dim3(1, 32, BATCH), 256, GEMM_SMEM>>>(
        xt, CH, (size_t)NPIX * CH, wp + CH * CH, CH, 0,
        kt, CH, (size_t)NPIX * CH, bk, CH);
    // V[c][n] = Wv[c][k] * X^T[n][k]^T + bv (row bias) -> fp16-split pack
    gemm_kernel<2><<<dim3(NPIX / BN, CH / BM, BATCH), 256, GEMM_SMEM>>>(
        wp + 2 * CH * CH, CH, 0, xt, CH, (size_t)NPIX * CH,
        vp, NPIX, (size_t)CH * NPIX, bv, CH);
    // scores[i][j] = Q^T[i][k] * K^T[j][k]^T
    gemm_kernel<0><<<dim3(NPIX / BN, NPIX / BM, BATCH), 256, GEMM_SMEM>>>(
        qt, CH, (size_t)NPIX * CH, kt, CH, (size_t)NPIX * CH,
        sc, NPIX, (size_t)NPIX * NPIX, nullptr, CH);
    softmax_kernel<<<BATCH * NPIX, 256>>>();
    // out[c][i] = V[c][j] * attn[i][j]^T
    av_gemm_kernel<<<dim3(NPIX / BN, CH / BM, BATCH), 256, OUT_SMEM>>>(vp, ah, out);
}